// round 10
// baseline (speedup 1.0000x reference)
#include <cuda_runtime.h>
#include <cstdint>

#define BATCH  16
#define NP     25200
#define TOPKN  2048
#define MAXDET 1000
#define CANDN  3072
#define ECAP   6144
#define NB     4096
#define IPB    128
#define STH    256
#define SN     1024
#define FULLM  0xffffffffu
typedef unsigned long long u64;

// ---------------- scratch ----------------
__device__ unsigned g_key32[BATCH * NP];   // (inv<<7)|cls, 0xFFFFFFFF = invalid
__device__ int      g_hist[BATCH * 132];   // bucket = inv>>17 (valid only); reset in k_sortnms

// ---------------- stage 1: thread-per-item score/class/key (256 thr, 128 items) ----------------
__global__ void __launch_bounds__(STH, 4) k_score(const float* __restrict__ pred) {
    __shared__ float s_data[IPB * 85 + 4];
    __shared__ int   s_h[128];
    int b   = blockIdx.y;
    int it0 = blockIdx.x * IPB;
    int nIt = min(IPB, NP - it0);
    int t = threadIdx.x;

    if (t < 128) s_h[t] = 0;

    // coalesced float4 staging (alignment-shifted)
    size_t base  = ((size_t)b * NP + it0) * 85;
    size_t first = base & ~(size_t)3;
    int shift = (int)(base - first);
    int nvec  = (shift + nIt * 85 + 3) >> 2;   // never OOB: total float count % 4 == 0
    const float4* src = (const float4*)(pred + first);
    float4* dst = (float4*)s_data;
    for (int i = t; i < nvec; i += STH) dst[i] = src[i];
    __syncthreads();

    if (t < nIt) {
        const float* p = s_data + shift + t * 85;   // stride 85: bank-conflict-free
        float obj = p[4];

        float m0 = p[5],  m1 = p[6],  m2 = p[7],  m3 = p[8];
        #pragma unroll
        for (int k = 9; k < 85; k += 4) {
            m0 = fmaxf(m0, p[k]);
            m1 = fmaxf(m1, p[k + 1]);
            m2 = fmaxf(m2, p[k + 2]);
            m3 = fmaxf(m3, p[k + 3]);
        }
        float bv = fmaxf(fmaxf(m0, m1), fmaxf(m2, m3));

        int bi = 0;
        #pragma unroll 8
        for (int k = 79; k >= 0; k--)
            if (p[5 + k] == bv) bi = k;

        float score = __fmul_rn(obj, bv);
        bool valid = (obj > 0.25f) && (score > 0.25f);
        unsigned kk = 0xFFFFFFFFu;
        if (valid) {
            unsigned inv = 0x3F800000u - __float_as_uint(score);  // < 0x1000000
            kk = (inv << 7) | (unsigned)bi;
            atomicAdd(&s_h[inv >> 17], 1);
        }
        g_key32[(size_t)b * NP + it0 + t] = kk;
    }
    __syncthreads();
    if (t < 128) {
        int v = s_h[t];
        if (v) atomicAdd(&g_hist[b * 132 + t], v);
    }
}

// ---------------- smem layout for k_sortnms (explicit overlays) ----------------
// region1 [0, 40960):      ck(12288) cv(12288) bhist(16384)  -> later sbox(32768)
// region2 [40960, 65536):  sk(12288) sv(12288)               -> later edges(24576)
// region3 [65536, 112640): obox(32768) score(8192) rnk(4096) cls8(2048)
#define OFF_CK    0
#define OFF_CV    12288
#define OFF_BH    24576
#define OFF_SBOX  0
#define OFF_SK    40960
#define OFF_SV    53248
#define OFF_EDGE  40960
#define OFF_OBOX  65536
#define OFF_SCORE 98304
#define OFF_RNK   106496
#define OFF_CLS   110592
#define DYN_TOTAL 112640

__device__ __forceinline__ u64 stab_key(unsigned k, unsigned v) {
    return ((u64)k << 16) | (u64)(v & 0xFFFFu);
}

__global__ void __launch_bounds__(SN) k_sortnms(const float* __restrict__ pred,
                                                float* __restrict__ out) {
    extern __shared__ char raw[];
    unsigned* ck   = (unsigned*)(raw + OFF_CK);
    unsigned* cv   = (unsigned*)(raw + OFF_CV);
    int*      bh   = (int*)     (raw + OFF_BH);
    unsigned* sk   = (unsigned*)(raw + OFF_SK);
    unsigned* sv   = (unsigned*)(raw + OFF_SV);
    float4*   sbox = (float4*)  (raw + OFF_SBOX);
    unsigned* edges= (unsigned*)(raw + OFF_EDGE);
    float4*   obox = (float4*)  (raw + OFF_OBOX);
    float*    score= (float*)   (raw + OFF_SCORE);
    unsigned short* rnk = (unsigned short*)(raw + OFF_RNK);
    unsigned char*  cls8= (unsigned char*) (raw + OFF_CLS);

    __shared__ int s_hist[128], s_wsum[32];
    __shared__ int s_cut, s_M;
    __shared__ int s_ccnt[81], s_cofs[81];
    __shared__ int s_ecnt, s_changed;
    __shared__ u64 s_keep[32], s_sup[32];
    __shared__ unsigned s_wbase[32], s_total;

    int b = blockIdx.x, t = threadIdx.x;
    int lane = t & 31, wid = t >> 5;

    if (t < 128) { s_hist[t] = g_hist[b * 132 + t]; g_hist[b * 132 + t] = 0; }
    __syncthreads();
    if (t == 0) {
        int cum = 0, c = 128;
        for (int i = 0; i < 128; i++) {
            cum += s_hist[i];
            if (cum >= TOPKN) { c = i; break; }
        }
        s_cut = c;
        s_ecnt = 0;
    }
    // clear bucket histogram while cutoff computes
    #pragma unroll
    for (int i = 0; i < NB / SN; i++) bh[t + SN * i] = 0;
    __syncthreads();
    unsigned cut = (unsigned)s_cut;
    unsigned limit = min((cut + 1u) << 17, 1u << 24);
    int end_bit = 32 - __clz(limit - 1u);
    int bsh = (end_bit > 12) ? (end_bit - 12) : 0;   // bucket = inv >> bsh < 4096

    // chunked idx-ordered compaction: thread t owns items [25t, 25t+25)
    const int CHUNK = (NP + SN - 1) / SN;   // 25
    int start = t * CHUNK;
    int lim = min(start + CHUNK, NP);
    int cnt = 0;
    for (int i = start; i < lim; i++)
        if ((g_key32[(size_t)b * NP + i] >> 24) <= cut) cnt++;
    int incl = cnt;
    #pragma unroll
    for (int d = 1; d < 32; d <<= 1) {
        int n = __shfl_up_sync(FULLM, incl, d);
        if (lane >= d) incl += n;
    }
    if (lane == 31) s_wsum[wid] = incl;
    __syncthreads();
    if (t < 32) {
        int v = s_wsum[t], inc2 = v;
        #pragma unroll
        for (int d = 1; d < 32; d <<= 1) {
            int n = __shfl_up_sync(FULLM, inc2, d);
            if (t >= d) inc2 += n;
        }
        s_wsum[t] = inc2 - v;
        if (t == 31) s_M = inc2;
    }
    __syncthreads();
    int off = s_wsum[wid] + incl - cnt;
    for (int i = start; i < lim; i++) {
        unsigned kk = g_key32[(size_t)b * NP + i];
        if ((kk >> 24) <= cut) {
            if (off < CANDN) {
                ck[off] = kk >> 7;                       // 25-bit inv
                cv[off] = (unsigned)i | ((kk & 0x7Fu) << 16);
            }
            off++;
        }
    }
    __syncthreads();
    int M = min(s_M, CANDN);

    // ---- bucket counting sort ----
    for (int i = t; i < M; i += SN) atomicAdd(&bh[ck[i] >> bsh], 1);
    __syncthreads();
    // hierarchical exclusive scan over 4096 buckets (4 per thread)
    {
        int b0 = bh[4 * t], b1 = bh[4 * t + 1], b2 = bh[4 * t + 2], b3 = bh[4 * t + 3];
        int sum = b0 + b1 + b2 + b3;
        int inc2 = sum;
        #pragma unroll
        for (int d = 1; d < 32; d <<= 1) {
            int n = __shfl_up_sync(FULLM, inc2, d);
            if (lane >= d) inc2 += n;
        }
        if (lane == 31) s_wsum[wid] = inc2;
        __syncthreads();
        if (t < 32) {
            int v = s_wsum[t], inc3 = v;
            #pragma unroll
            for (int d = 1; d < 32; d <<= 1) {
                int n = __shfl_up_sync(FULLM, inc3, d);
                if (t >= d) inc3 += n;
            }
            s_wsum[t] = inc3 - v;
        }
        __syncthreads();
        int base = s_wsum[wid] + inc2 - sum;
        bh[4 * t]     = base;
        bh[4 * t + 1] = base + b0;
        bh[4 * t + 2] = base + b0 + b1;
        bh[4 * t + 3] = base + b0 + b1 + b2;
    }
    __syncthreads();
    // scatter (unordered within bucket; cleanup restores total order)
    for (int i = t; i < M; i += SN) {
        unsigned k = ck[i], v = cv[i];
        int pos = atomicAdd(&bh[k >> bsh], 1);
        sk[pos] = k; sv[pos] = v;
    }
    __syncthreads();
    // cleanup: insertion sort each bucket segment by (inv, idx); bh[x] now = segment end
    for (int bb = t; bb < NB; bb += SN) {
        int st = (bb == 0) ? 0 : bh[bb - 1];
        int en = bh[bb];
        for (int x = st + 1; x < en; x++) {
            unsigned tk = sk[x], tv = sv[x];
            u64 kx = stab_key(tk, tv);
            int y = x - 1;
            while (y >= st && stab_key(sk[y], sv[y]) > kx) {
                sk[y + 1] = sk[y]; sv[y + 1] = sv[y]; y--;
            }
            sk[y + 1] = tk; sv[y + 1] = tv;
        }
    }
    if (t < 81) s_ccnt[t] = 0;
    __syncthreads();
    int total = min(M, TOPKN);

    // gather top-2048 into smem (rank-ordered)
    #pragma unroll
    for (int rr = 0; rr < TOPKN / SN; rr++) {
        int r = t + SN * rr;
        if (r >= total) {
            obox[r]  = make_float4(0.f, 0.f, 0.f, 0.f);
            score[r] = 0.f;
            cls8[r]  = 0;
            continue;
        }
        int idx = (int)(sv[r] & 0xFFFFu);
        int cls = (int)((sv[r] >> 16) & 0x7Fu);
        float s = __uint_as_float(0x3F800000u - sk[r]);

        const float* p = pred + ((size_t)b * NP + idx) * 85;
        float cx = p[0], cy = p[1], w = p[2], h = p[3];
        float x1 = __fsub_rn(cx, __fmul_rn(w, 0.5f));
        float y1 = __fsub_rn(cy, __fmul_rn(h, 0.5f));
        float x2 = __fadd_rn(cx, __fmul_rn(w, 0.5f));
        float y2 = __fadd_rn(cy, __fmul_rn(h, 0.5f));

        obox[r]  = make_float4(x1, y1, x2, y2);
        score[r] = s;
        cls8[r]  = (unsigned char)cls;
        atomicAdd(&s_ccnt[cls], 1);
    }
    __syncthreads();
    if (t == 0) {
        int run = 0;
        for (int c = 0; c < 80; c++) { s_cofs[c] = run; run += s_ccnt[c]; }
        s_cofs[80] = run;
    }
    __syncthreads();
    if (t < 80) s_ccnt[t] = s_cofs[t];   // running positions
    __syncthreads();

    // class-grouped scatter of shifted boxes (overlays dead ck/cv/bh region)
    #pragma unroll
    for (int rr = 0; rr < TOPKN / SN; rr++) {
        int r = t + SN * rr;
        if (r >= total) continue;
        int cls = (int)((sv[r] >> 16) & 0x7Fu);
        int slot = atomicAdd(&s_ccnt[cls], 1);
        float4 bx = obox[r];
        float c = __fmul_rn((float)cls, 4096.0f);
        sbox[slot] = make_float4(__fadd_rn(bx.x, c), __fadd_rn(bx.y, c),
                                 __fadd_rn(bx.z, c), __fadd_rn(bx.w, c));
        rnk[slot] = (unsigned short)r;
    }
    __syncthreads();

    // within-class pairs flattened across lanes; 32 warps over 80 classes
    for (int c = wid; c < 80; c += 32) {
        int lo = s_cofs[c], n = s_cofs[c + 1] - lo;
        int npairs = (n * (n - 1)) >> 1;
        for (int p = lane; p < npairs; p += 32) {
            int j = (int)(0.5f * (1.0f + sqrtf(8.0f * (float)p + 1.0f)));
            while ((j * (j - 1)) >> 1 > p) j--;
            while ((j * (j + 1)) >> 1 <= p) j++;
            int i = p - ((j * (j - 1)) >> 1);

            float4 A = sbox[lo + j];
            float4 B = sbox[lo + i];
            float ltx = fmaxf(A.x, B.x);
            float lty = fmaxf(A.y, B.y);
            float rbx = fminf(A.z, B.z);
            float rby = fminf(A.w, B.w);
            float ww = fmaxf(__fsub_rn(rbx, ltx), 0.0f);
            float hh = fmaxf(__fsub_rn(rby, lty), 0.0f);
            float inter = __fmul_rn(ww, hh);
            if (inter > 0.0f) {
                float areaA = __fmul_rn(__fsub_rn(A.z, A.x), __fsub_rn(A.w, A.y));
                float areaB = __fmul_rn(__fsub_rn(B.z, B.x), __fsub_rn(B.w, B.y));
                float denom = __fadd_rn(__fsub_rn(__fadd_rn(areaA, areaB), inter), 1e-7f);
                bool bit;
                if (inter > __fmul_rn(0.4501f, denom))       bit = true;
                else if (inter <= __fmul_rn(0.4499f, denom)) bit = false;
                else bit = (__fdiv_rn(inter, denom) > 0.45f);
                if (bit) {
                    int ri = rnk[lo + i], rj = rnk[lo + j];
                    int lw = min(ri, rj), hi = max(ri, rj);
                    int pos = atomicAdd(&s_ecnt, 1);
                    if (pos < ECAP)
                        edges[pos] = ((unsigned)lw << 16) | (unsigned)hi;
                }
            }
        }
    }
    __syncthreads();
    int E = min(s_ecnt, ECAP);

    if (t < 32) {
        int base = t * 64;
        s_keep[t] = (total >= base + 64) ? ~0ull
                  : (total <= base) ? 0ull : ((1ull << (total - base)) - 1ull);
    }
    __syncthreads();

    // Jacobi fixpoint of keep[j] = valid[j] & !exists edge(i,j) with keep[i] (DAG, i<j)
    int changed;
    do {
        if (t < 32) s_sup[t] = 0ull;
        __syncthreads();
        for (int e = t; e < E; e += SN) {
            unsigned ed = edges[e];
            int i = (int)(ed >> 16), j = (int)(ed & 0xFFFFu);
            if ((s_keep[i >> 6] >> (i & 63)) & 1ull)
                atomicOr(&s_sup[j >> 6], 1ull << (j & 63));
        }
        __syncthreads();
        if (t == 0) s_changed = 0;
        __syncthreads();
        if (t < 32) {
            int base = t * 64;
            u64 valid = (total >= base + 64) ? ~0ull
                      : (total <= base) ? 0ull : ((1ull << (total - base)) - 1ull);
            u64 nk = valid & ~s_sup[t];
            if (nk != s_keep[t]) { s_keep[t] = nk; s_changed = 1; }
        }
        __syncthreads();
        changed = s_changed;
    } while (changed);

    // per-word base ranks
    if (wid == 0) {
        unsigned cnt2 = (unsigned)__popcll(s_keep[lane]), incl2 = cnt2;
        #pragma unroll
        for (int d = 1; d < 32; d <<= 1) {
            unsigned n = __shfl_up_sync(FULLM, incl2, d);
            if (lane >= d) incl2 += n;
        }
        s_wbase[lane] = incl2 - cnt2;
        if (lane == 31) s_total = incl2;
    }
    __syncthreads();

    // parallel compaction of survivors (rank order == score order)
    #pragma unroll
    for (int r = 0; r < TOPKN / SN; r++) {
        int gbit = t + SN * r;
        int word = gbit >> 6, bit = gbit & 63;
        u64 kw = s_keep[word];
        if ((kw >> bit) & 1ull) {
            unsigned rank = s_wbase[word] +
                            (unsigned)__popcll(kw & (((u64)1 << bit) - 1ull));
            if (rank < MAXDET) {
                float4 bx = obox[gbit];
                float* o = out + ((size_t)b * MAXDET + rank) * 6;
                o[0] = bx.x; o[1] = bx.y; o[2] = bx.z; o[3] = bx.w;
                o[4] = score[gbit];
                o[5] = (float)cls8[gbit];
            }
        }
    }
    unsigned fillstart = min(s_total, (unsigned)MAXDET);
    for (unsigned m = fillstart + t; m < MAXDET; m += SN) {
        float* o = out + ((size_t)b * MAXDET + m) * 6;
        o[0] = 0.f; o[1] = 0.f; o[2] = 0.f; o[3] = 0.f; o[4] = 0.f; o[5] = -1.f;
    }
}

// ---------------- launch ----------------
extern "C" void kernel_launch(void* const* d_in, const int* in_sizes, int n_in,
                              void* d_out, int out_size) {
    (void)in_sizes; (void)n_in; (void)out_size;
    const float* pred = (const float*)d_in[0];
    float* out = (float*)d_out;

    static bool attr_set = false;
    if (!attr_set) {
        cudaFuncSetAttribute(k_sortnms, cudaFuncAttributeMaxDynamicSharedMemorySize,
                             DYN_TOTAL);
        attr_set = true;
    }

    k_score<<<dim3((NP + IPB - 1) / IPB, BATCH), STH>>>(pred);
    k_sortnms<<<BATCH, SN, DYN_TOTAL>>>(pred, out);
}

// round 11
// speedup vs baseline: 1.3020x; 1.3020x over previous
#include <cuda_runtime.h>
#include <cub/cub.cuh>
#include <cstdint>

#define BATCH  16
#define NP     25200
#define TOPKN  2048
#define MAXDET 1000
#define CANDN  3072
#define ECAP   6144
#define IPB    128
#define STH    256
#define SN     1024
#define NR     25          // ceil(NP / SN)
#define FULLM  0xffffffffu
typedef unsigned long long u64;

// ---------------- scratch ----------------
__device__ unsigned g_key32[BATCH * NP];   // (inv<<7)|cls, 0xFFFFFFFF = invalid
__device__ int      g_hist[BATCH * 132];   // bucket = inv>>17 (valid only); reset in k_sortnms

// ---------------- stage 1: thread-per-item score/class/key (256 thr, 128 items) ----------------
__global__ void __launch_bounds__(STH, 4) k_score(const float* __restrict__ pred) {
    __shared__ float s_data[IPB * 85 + 4];
    __shared__ int   s_h[128];
    int b   = blockIdx.y;
    int it0 = blockIdx.x * IPB;
    int nIt = min(IPB, NP - it0);
    int t = threadIdx.x;

    if (t < 128) s_h[t] = 0;

    // coalesced float4 staging (alignment-shifted)
    size_t base  = ((size_t)b * NP + it0) * 85;
    size_t first = base & ~(size_t)3;
    int shift = (int)(base - first);
    int nvec  = (shift + nIt * 85 + 3) >> 2;   // never OOB: total float count % 4 == 0
    const float4* src = (const float4*)(pred + first);
    float4* dst = (float4*)s_data;
    for (int i = t; i < nvec; i += STH) dst[i] = src[i];
    __syncthreads();

    if (t < nIt) {
        const float* p = s_data + shift + t * 85;   // stride 85: bank-conflict-free
        float obj = p[4];

        float m0 = p[5],  m1 = p[6],  m2 = p[7],  m3 = p[8];
        #pragma unroll
        for (int k = 9; k < 85; k += 4) {
            m0 = fmaxf(m0, p[k]);
            m1 = fmaxf(m1, p[k + 1]);
            m2 = fmaxf(m2, p[k + 2]);
            m3 = fmaxf(m3, p[k + 3]);
        }
        float bv = fmaxf(fmaxf(m0, m1), fmaxf(m2, m3));

        int bi = 0;
        #pragma unroll 8
        for (int k = 79; k >= 0; k--)
            if (p[5 + k] == bv) bi = k;

        float score = __fmul_rn(obj, bv);
        bool valid = (obj > 0.25f) && (score > 0.25f);
        unsigned kk = 0xFFFFFFFFu;
        if (valid) {
            unsigned inv = 0x3F800000u - __float_as_uint(score);  // < 0x1000000
            kk = (inv << 7) | (unsigned)bi;
            atomicAdd(&s_h[inv >> 17], 1);
        }
        g_key32[(size_t)b * NP + it0 + t] = kk;
    }
    __syncthreads();
    if (t < 128) {
        int v = s_h[t];
        if (v) atomicAdd(&g_hist[b * 132 + t], v);
    }
}

// ---------------- stage 2: cutoff+compact+sort+gather+class-group+IoU+greedy+output ----------------
typedef cub::BlockRadixSort<unsigned, SN, 3, unsigned> BRS;
struct SMem {
    union {
        struct { unsigned ck[CANDN]; unsigned cv[CANDN]; } c;   // pre-sort staging
        BRS::TempStorage sort;                                  // sort temp
        float4 sbox[TOPKN];                                     // shifted, class-grouped (post-sort)
    } a;
    float4        obox[TOPKN];      // unshifted, rank-ordered
    float         score[TOPKN];
    unsigned short rnk[TOPKN];      // class-grouped -> rank
    unsigned char cls8[TOPKN];
    unsigned      edges[ECAP];
};

__global__ void __launch_bounds__(SN) k_sortnms(const float* __restrict__ pred,
                                                float* __restrict__ out) {
    extern __shared__ char raw[];
    SMem* sm = (SMem*)raw;
    __shared__ int s_cnt[NR * 32];           // per-(round, warp) counts -> bases
    __shared__ int s_hist[128], s_wsum[32];
    __shared__ int s_cut, s_M;
    __shared__ int s_ccnt[81], s_cofs[81];
    __shared__ int s_ecnt, s_changed;
    __shared__ u64 s_keep[32], s_sup[32];
    __shared__ unsigned s_wbase[32], s_total;

    int b = blockIdx.x, t = threadIdx.x;
    int lane = t & 31, wid = t >> 5;
    size_t bNP = (size_t)b * NP;

    if (t < 128) { s_hist[t] = g_hist[b * 132 + t]; g_hist[b * 132 + t] = 0; }
    __syncthreads();
    if (t == 0) {
        int cum = 0, c = 128;
        for (int i = 0; i < 128; i++) {
            cum += s_hist[i];
            if (cum >= TOPKN) { c = i; break; }
        }
        s_cut = c;
        s_ecnt = 0;
    }
    __syncthreads();
    unsigned cut = (unsigned)s_cut;
    unsigned limit = min((cut + 1u) << 17, 1u << 24);
    int end_bit = 32 - __clz(limit - 1u);

    // ---- coalesced idx-ordered compaction (3 barriers) ----
    // phase A: flags + per-(round,warp) counts; item idx = r*SN + t (round-major == idx order)
    unsigned flags = 0;
    #pragma unroll
    for (int r = 0; r < NR; r++) {
        int i = r * SN + t;
        bool f = (i < NP) && ((g_key32[bNP + i] >> 24) <= cut);
        unsigned bal = __ballot_sync(FULLM, f);
        if (f) flags |= 1u << r;
        if (lane == 0) s_cnt[r * 32 + wid] = __popc(bal);
    }
    __syncthreads();
    // one hierarchical exclusive scan over the 800 (r,w) entries
    {
        int v = (t < NR * 32) ? s_cnt[t] : 0;
        int inc = v;
        #pragma unroll
        for (int d = 1; d < 32; d <<= 1) {
            int n = __shfl_up_sync(FULLM, inc, d);
            if (lane >= d) inc += n;
        }
        if (lane == 31) s_wsum[wid] = inc;
        __syncthreads();
        if (t < 32) {
            int v2 = s_wsum[t], inc2 = v2;
            #pragma unroll
            for (int d = 1; d < 32; d <<= 1) {
                int n = __shfl_up_sync(FULLM, inc2, d);
                if (t >= d) inc2 += n;
            }
            s_wsum[t] = inc2 - v2;
        }
        __syncthreads();
        int base = s_wsum[wid] + inc - v;
        if (t < NR * 32) s_cnt[t] = base;
        if (t == NR * 32 - 1) s_M = base + v;
        __syncthreads();
    }
    // phase B: coalesced re-read (L1-hot) + ordered write
    #pragma unroll
    for (int r = 0; r < NR; r++) {
        bool f = (flags >> r) & 1u;
        unsigned bal = __ballot_sync(FULLM, f);
        if (f) {
            int pos = s_cnt[r * 32 + wid] + __popc(bal & ((1u << lane) - 1u));
            if (pos < CANDN) {
                unsigned kk = g_key32[bNP + r * SN + t];
                sm->a.c.ck[pos] = kk >> 7;                       // 25-bit inv
                sm->a.c.cv[pos] = (unsigned)(r * SN + t) | ((kk & 0x7Fu) << 16);
            }
        }
    }
    __syncthreads();
    int M = min(s_M, CANDN);

    unsigned keys[3], vals[3];
    #pragma unroll
    for (int i = 0; i < 3; i++) {
        int r = t * 3 + i;
        keys[i] = (r < M) ? sm->a.c.ck[r] : (limit - 1u);  // pad: max key within end_bit
        vals[i] = (r < M) ? sm->a.c.cv[r] : 0xFFFFFFFFu;   // sentinel marks padding
    }
    __syncthreads();
    // stable ascending sort on inv (end_bit bits); idx-order compaction = tie-break;
    // pads tie at max key but follow all real items (stability).
    BRS(sm->a.sort).Sort(keys, vals, 0, end_bit);

    if (t < 81) s_ccnt[t] = 0;
    __syncthreads();

    // gather top-2048 into smem (rank-ordered)
    #pragma unroll
    for (int i = 0; i < 3; i++) {
        int r = t * 3 + i;
        if (r >= TOPKN) continue;
        if (vals[i] >> 31) {                // padding
            sm->obox[r]  = make_float4(0.f, 0.f, 0.f, 0.f);
            sm->score[r] = 0.f;
            sm->cls8[r]  = 0;
            continue;
        }
        int idx = (int)(vals[i] & 0xFFFFu);
        int cls = (int)((vals[i] >> 16) & 0x7Fu);
        float s = __uint_as_float(0x3F800000u - keys[i]);

        const float* p = pred + (bNP + idx) * 85;
        float cx = p[0], cy = p[1], w = p[2], h = p[3];
        float x1 = __fsub_rn(cx, __fmul_rn(w, 0.5f));
        float y1 = __fsub_rn(cy, __fmul_rn(h, 0.5f));
        float x2 = __fadd_rn(cx, __fmul_rn(w, 0.5f));
        float y2 = __fadd_rn(cy, __fmul_rn(h, 0.5f));

        sm->obox[r]  = make_float4(x1, y1, x2, y2);
        sm->score[r] = s;
        sm->cls8[r]  = (unsigned char)cls;
        atomicAdd(&s_ccnt[cls], 1);
    }
    __syncthreads();
    if (t == 0) {
        int run = 0;
        for (int c = 0; c < 80; c++) { s_cofs[c] = run; run += s_ccnt[c]; }
        s_cofs[80] = run;
    }
    __syncthreads();
    int total = s_cofs[80];
    if (t < 80) s_ccnt[t] = s_cofs[t];   // running positions
    __syncthreads();

    // class-grouped scatter of shifted boxes (overlays dead sort temp)
    #pragma unroll
    for (int i = 0; i < 3; i++) {
        int r = t * 3 + i;
        if (r >= TOPKN || (vals[i] >> 31)) continue;
        int cls = (int)((vals[i] >> 16) & 0x7Fu);
        int slot = atomicAdd(&s_ccnt[cls], 1);
        float4 bx = sm->obox[r];
        float c = __fmul_rn((float)cls, 4096.0f);
        sm->a.sbox[slot] = make_float4(__fadd_rn(bx.x, c), __fadd_rn(bx.y, c),
                                       __fadd_rn(bx.z, c), __fadd_rn(bx.w, c));
        sm->rnk[slot] = (unsigned short)r;
    }
    __syncthreads();

    // within-class pairs flattened across lanes; 32 warps over 80 classes
    for (int c = wid; c < 80; c += 32) {
        int lo = s_cofs[c], n = s_cofs[c + 1] - lo;
        int npairs = (n * (n - 1)) >> 1;
        for (int p = lane; p < npairs; p += 32) {
            int j = (int)(0.5f * (1.0f + sqrtf(8.0f * (float)p + 1.0f)));
            while ((j * (j - 1)) >> 1 > p) j--;
            while ((j * (j + 1)) >> 1 <= p) j++;
            int i = p - ((j * (j - 1)) >> 1);

            float4 A = sm->a.sbox[lo + j];
            float4 B = sm->a.sbox[lo + i];
            float ltx = fmaxf(A.x, B.x);
            float lty = fmaxf(A.y, B.y);
            float rbx = fminf(A.z, B.z);
            float rby = fminf(A.w, B.w);
            float ww = fmaxf(__fsub_rn(rbx, ltx), 0.0f);
            float hh = fmaxf(__fsub_rn(rby, lty), 0.0f);
            float inter = __fmul_rn(ww, hh);
            if (inter > 0.0f) {
                float areaA = __fmul_rn(__fsub_rn(A.z, A.x), __fsub_rn(A.w, A.y));
                float areaB = __fmul_rn(__fsub_rn(B.z, B.x), __fsub_rn(B.w, B.y));
                float denom = __fadd_rn(__fsub_rn(__fadd_rn(areaA, areaB), inter), 1e-7f);
                bool bit;
                if (inter > __fmul_rn(0.4501f, denom))       bit = true;
                else if (inter <= __fmul_rn(0.4499f, denom)) bit = false;
                else bit = (__fdiv_rn(inter, denom) > 0.45f);
                if (bit) {
                    int ri = sm->rnk[lo + i], rj = sm->rnk[lo + j];
                    int lw = min(ri, rj), hi = max(ri, rj);
                    int pos = atomicAdd(&s_ecnt, 1);
                    if (pos < ECAP)
                        sm->edges[pos] = ((unsigned)lw << 16) | (unsigned)hi;
                }
            }
        }
    }
    __syncthreads();
    int E = min(s_ecnt, ECAP);

    if (t < 32) {
        int base = t * 64;
        s_keep[t] = (total >= base + 64) ? ~0ull
                  : (total <= base) ? 0ull : ((1ull << (total - base)) - 1ull);
    }
    __syncthreads();

    // Jacobi fixpoint of keep[j] = valid[j] & !exists edge(i,j) with keep[i] (DAG, i<j)
    int changed;
    do {
        if (t < 32) s_sup[t] = 0ull;
        __syncthreads();
        for (int e = t; e < E; e += SN) {
            unsigned ed = sm->edges[e];
            int i = (int)(ed >> 16), j = (int)(ed & 0xFFFFu);
            if ((s_keep[i >> 6] >> (i & 63)) & 1ull)
                atomicOr(&s_sup[j >> 6], 1ull << (j & 63));
        }
        __syncthreads();
        if (t == 0) s_changed = 0;
        __syncthreads();
        if (t < 32) {
            int base = t * 64;
            u64 valid = (total >= base + 64) ? ~0ull
                      : (total <= base) ? 0ull : ((1ull << (total - base)) - 1ull);
            u64 nk = valid & ~s_sup[t];
            if (nk != s_keep[t]) { s_keep[t] = nk; s_changed = 1; }
        }
        __syncthreads();
        changed = s_changed;
    } while (changed);

    // per-word base ranks
    if (wid == 0) {
        unsigned cnt2 = (unsigned)__popcll(s_keep[lane]), incl2 = cnt2;
        #pragma unroll
        for (int d = 1; d < 32; d <<= 1) {
            unsigned n = __shfl_up_sync(FULLM, incl2, d);
            if (lane >= d) incl2 += n;
        }
        s_wbase[lane] = incl2 - cnt2;
        if (lane == 31) s_total = incl2;
    }
    __syncthreads();

    // parallel compaction of survivors (rank order == score order)
    #pragma unroll
    for (int r = 0; r < 2; r++) {
        int gbit = t + SN * r;
        int word = gbit >> 6, bit = gbit & 63;
        u64 kw = s_keep[word];
        if ((kw >> bit) & 1ull) {
            unsigned rank = s_wbase[word] +
                            (unsigned)__popcll(kw & (((u64)1 << bit) - 1ull));
            if (rank < MAXDET) {
                float4 bx = sm->obox[gbit];
                float* o = out + ((size_t)b * MAXDET + rank) * 6;
                o[0] = bx.x; o[1] = bx.y; o[2] = bx.z; o[3] = bx.w;
                o[4] = sm->score[gbit];
                o[5] = (float)sm->cls8[gbit];
            }
        }
    }
    unsigned fillstart = min(s_total, (unsigned)MAXDET);
    for (unsigned m = fillstart + t; m < MAXDET; m += SN) {
        float* o = out + ((size_t)b * MAXDET + m) * 6;
        o[0] = 0.f; o[1] = 0.f; o[2] = 0.f; o[3] = 0.f; o[4] = 0.f; o[5] = -1.f;
    }
}

// ---------------- launch ----------------
extern "C" void kernel_launch(void* const* d_in, const int* in_sizes, int n_in,
                              void* d_out, int out_size) {
    (void)in_sizes; (void)n_in; (void)out_size;
    const float* pred = (const float*)d_in[0];
    float* out = (float*)d_out;

    static bool attr_set = false;
    if (!attr_set) {
        cudaFuncSetAttribute(k_sortnms, cudaFuncAttributeMaxDynamicSharedMemorySize,
                             (int)sizeof(SMem));
        attr_set = true;
    }

    k_score<<<dim3((NP + IPB - 1) / IPB, BATCH), STH>>>(pred);
    k_sortnms<<<BATCH, SN, sizeof(SMem)>>>(pred, out);
}

// round 12
// speedup vs baseline: 1.3828x; 1.0620x over previous
#include <cuda_runtime.h>
#include <cstdint>

#define BATCH  16
#define NP     25200
#define TOPKN  2048
#define MAXDET 1000
#define CANDN  3072
#define ECAP   6144
#define IPB    128
#define STH    256
#define SN     1024
#define NR     25          // ceil(NP / SN)
#define FULLM  0xffffffffu
typedef unsigned long long u64;

// ---------------- scratch ----------------
__device__ unsigned g_key32[BATCH * NP];   // (inv<<7)|cls, 0xFFFFFFFF = invalid
__device__ int      g_hist[BATCH * 132];   // bucket = inv>>17 (valid only); reset in k_sortnms

// ---------------- stage 1: thread-per-item score/class/key (256 thr, 128 items) ----------------
__global__ void __launch_bounds__(STH, 4) k_score(const float* __restrict__ pred) {
    __shared__ float s_data[IPB * 85 + 4];
    __shared__ int   s_h[128];
    int b   = blockIdx.y;
    int it0 = blockIdx.x * IPB;
    int nIt = min(IPB, NP - it0);
    int t = threadIdx.x;

    if (t < 128) s_h[t] = 0;

    size_t base  = ((size_t)b * NP + it0) * 85;
    size_t first = base & ~(size_t)3;
    int shift = (int)(base - first);
    int nvec  = (shift + nIt * 85 + 3) >> 2;   // never OOB: total float count % 4 == 0
    const float4* src = (const float4*)(pred + first);
    float4* dst = (float4*)s_data;
    for (int i = t; i < nvec; i += STH) dst[i] = src[i];
    __syncthreads();

    if (t < nIt) {
        const float* p = s_data + shift + t * 85;   // stride 85: bank-conflict-free
        float obj = p[4];

        float m0 = p[5],  m1 = p[6],  m2 = p[7],  m3 = p[8];
        #pragma unroll
        for (int k = 9; k < 85; k += 4) {
            m0 = fmaxf(m0, p[k]);
            m1 = fmaxf(m1, p[k + 1]);
            m2 = fmaxf(m2, p[k + 2]);
            m3 = fmaxf(m3, p[k + 3]);
        }
        float bv = fmaxf(fmaxf(m0, m1), fmaxf(m2, m3));

        int bi = 0;
        #pragma unroll 8
        for (int k = 79; k >= 0; k--)
            if (p[5 + k] == bv) bi = k;

        float score = __fmul_rn(obj, bv);
        bool valid = (obj > 0.25f) && (score > 0.25f);
        unsigned kk = 0xFFFFFFFFu;
        if (valid) {
            unsigned inv = 0x3F800000u - __float_as_uint(score);  // < 0x1000000
            kk = (inv << 7) | (unsigned)bi;
            atomicAdd(&s_h[inv >> 17], 1);
        }
        g_key32[(size_t)b * NP + it0 + t] = kk;
    }
    __syncthreads();
    if (t < 128) {
        int v = s_h[t];
        if (v) atomicAdd(&g_hist[b * 132 + t], v);
    }
}

// ---------------- smem layout for k_sortnms (explicit overlays) ----------------
// ck/cv   [0, 24576)        compaction staging (dead after bucket scatter)
// sk/sv   [24576, 49152)    bucket-scattered   (dead after rank sort)
// fk/fv   [49152, 73728)    final sorted       (dead after class-scatter)
// sbox    [0, 32768)        overlays ck/cv+sk  (written in class-scatter)
// edges   [32768, 57344)    overlays sv+fk     (written in IoU phase)
// obox    [73728, 106496)   score [106496, 114688)  rnk [114688, 118784)  cls8 [118784, 120832)
#define OFF_CK    0
#define OFF_CV    12288
#define OFF_SK    24576
#define OFF_SV    36864
#define OFF_FK    49152
#define OFF_FV    61440
#define OFF_SBOX  0
#define OFF_EDGE  32768
#define OFF_OBOX  73728
#define OFF_SCORE 106496
#define OFF_RNK   114688
#define OFF_CLS   118784
#define DYN_TOTAL 120832

__global__ void __launch_bounds__(SN) k_sortnms(const float* __restrict__ pred,
                                                float* __restrict__ out) {
    extern __shared__ char raw[];
    unsigned* ck   = (unsigned*)(raw + OFF_CK);
    unsigned* cv   = (unsigned*)(raw + OFF_CV);
    unsigned* sk   = (unsigned*)(raw + OFF_SK);
    unsigned* sv   = (unsigned*)(raw + OFF_SV);
    unsigned* fk   = (unsigned*)(raw + OFF_FK);
    unsigned* fv   = (unsigned*)(raw + OFF_FV);
    float4*   sbox = (float4*)  (raw + OFF_SBOX);
    unsigned* edges= (unsigned*)(raw + OFF_EDGE);
    float4*   obox = (float4*)  (raw + OFF_OBOX);
    float*    score= (float*)   (raw + OFF_SCORE);
    unsigned short* rnk = (unsigned short*)(raw + OFF_RNK);
    unsigned char*  cls8= (unsigned char*) (raw + OFF_CLS);

    __shared__ int s_cnt[NR * 32];           // per-(round, warp) counts -> bases
    __shared__ int s_bh[256];                // bucket histogram -> running ends
    __shared__ int s_hist[128], s_wsum[32];
    __shared__ int s_cut, s_M;
    __shared__ int s_ccnt[81], s_cofs[81];
    __shared__ int s_ecnt, s_changed;
    __shared__ u64 s_keep[32], s_sup[32];
    __shared__ unsigned s_wbase[32], s_total;

    int b = blockIdx.x, t = threadIdx.x;
    int lane = t & 31, wid = t >> 5;
    size_t bNP = (size_t)b * NP;

    if (t < 128) { s_hist[t] = g_hist[b * 132 + t]; g_hist[b * 132 + t] = 0; }
    if (t < 256) s_bh[t] = 0;
    __syncthreads();
    if (t == 0) {
        int cum = 0, c = 128;
        for (int i = 0; i < 128; i++) {
            cum += s_hist[i];
            if (cum >= TOPKN) { c = i; break; }
        }
        s_cut = c;
        s_ecnt = 0;
    }
    __syncthreads();
    unsigned cut = (unsigned)s_cut;
    unsigned limit = min((cut + 1u) << 17, 1u << 24);
    int end_bit = 32 - __clz(limit - 1u);
    int bsh = (end_bit > 8) ? (end_bit - 8) : 0;   // bucket = inv >> bsh < 256

    // ---- coalesced idx-ordered compaction (3 barriers) ----
    unsigned flags = 0;
    #pragma unroll
    for (int r = 0; r < NR; r++) {
        int i = r * SN + t;
        bool f = (i < NP) && ((g_key32[bNP + i] >> 24) <= cut);
        unsigned bal = __ballot_sync(FULLM, f);
        if (f) flags |= 1u << r;
        if (lane == 0) s_cnt[r * 32 + wid] = __popc(bal);
    }
    __syncthreads();
    {
        int v = (t < NR * 32) ? s_cnt[t] : 0;
        int inc = v;
        #pragma unroll
        for (int d = 1; d < 32; d <<= 1) {
            int n = __shfl_up_sync(FULLM, inc, d);
            if (lane >= d) inc += n;
        }
        if (lane == 31) s_wsum[wid] = inc;
        __syncthreads();
        if (t < 32) {
            int v2 = s_wsum[t], inc2 = v2;
            #pragma unroll
            for (int d = 1; d < 32; d <<= 1) {
                int n = __shfl_up_sync(FULLM, inc2, d);
                if (t >= d) inc2 += n;
            }
            s_wsum[t] = inc2 - v2;
        }
        __syncthreads();
        int base = s_wsum[wid] + inc - v;
        if (t < NR * 32) s_cnt[t] = base;
        if (t == NR * 32 - 1) s_M = base + v;
        __syncthreads();
    }
    #pragma unroll
    for (int r = 0; r < NR; r++) {
        bool f = (flags >> r) & 1u;
        unsigned bal = __ballot_sync(FULLM, f);
        if (f) {
            int pos = s_cnt[r * 32 + wid] + __popc(bal & ((1u << lane) - 1u));
            if (pos < CANDN) {
                unsigned kk = g_key32[bNP + r * SN + t];
                ck[pos] = kk >> 7;                       // 25-bit inv
                cv[pos] = (unsigned)(r * SN + t) | ((kk & 0x7Fu) << 16);
            }
        }
    }
    __syncthreads();
    int M = min(s_M, CANDN);

    // ---- 256-bucket MSD scatter + warp-parallel exact-rank sort ----
    for (int i = t; i < M; i += SN) atomicAdd(&s_bh[ck[i] >> bsh], 1);
    __syncthreads();
    if (t < 32) {   // one-warp scan over 256 buckets, 8 per lane
        int loc[8], run = 0;
        #pragma unroll
        for (int k = 0; k < 8; k++) { loc[k] = run; run += s_bh[t * 8 + k]; }
        int inc = run;
        #pragma unroll
        for (int d = 1; d < 32; d <<= 1) {
            int n = __shfl_up_sync(FULLM, inc, d);
            if (t >= d) inc += n;
        }
        int base = inc - run;
        #pragma unroll
        for (int k = 0; k < 8; k++) s_bh[t * 8 + k] = base + loc[k];
    }
    __syncthreads();
    for (int i = t; i < M; i += SN) {   // scatter (unordered within bucket)
        unsigned k = ck[i], v = cv[i];
        int pos = atomicAdd(&s_bh[k >> bsh], 1);
        sk[pos] = k; sv[pos] = v;
    }
    __syncthreads();
    // per-bucket exact-rank sort; keys (inv<<15|idx) are all distinct -> deterministic
    #pragma unroll
    for (int k8 = 0; k8 < 8; k8++) {
        int bb = wid * 8 + k8;
        int st = (bb == 0) ? 0 : s_bh[bb - 1];
        int en = s_bh[bb];
        for (int x = st + lane; x < en; x += 32) {
            unsigned kx = sk[x], vx = sv[x];
            u64 key = ((u64)kx << 15) | (u64)(vx & 0x7FFFu);
            int rank = 0;
            for (int y = st; y < en; y++) {
                u64 ky = ((u64)sk[y] << 15) | (u64)(sv[y] & 0x7FFFu);
                rank += (ky < key);
            }
            fk[st + rank] = kx; fv[st + rank] = vx;
        }
    }
    if (t < 81) s_ccnt[t] = 0;
    __syncthreads();
    int total = min(M, TOPKN);

    // ---- gather top-2048 into smem (rank-ordered) ----
    #pragma unroll
    for (int rr = 0; rr < TOPKN / SN; rr++) {
        int r = t + SN * rr;
        if (r >= total) {
            obox[r]  = make_float4(0.f, 0.f, 0.f, 0.f);
            score[r] = 0.f;
            cls8[r]  = 0;
            continue;
        }
        int idx = (int)(fv[r] & 0xFFFFu);
        int cls = (int)((fv[r] >> 16) & 0x7Fu);
        float s = __uint_as_float(0x3F800000u - fk[r]);

        const float* p = pred + (bNP + idx) * 85;
        float cx = p[0], cy = p[1], w = p[2], h = p[3];
        float x1 = __fsub_rn(cx, __fmul_rn(w, 0.5f));
        float y1 = __fsub_rn(cy, __fmul_rn(h, 0.5f));
        float x2 = __fadd_rn(cx, __fmul_rn(w, 0.5f));
        float y2 = __fadd_rn(cy, __fmul_rn(h, 0.5f));

        obox[r]  = make_float4(x1, y1, x2, y2);
        score[r] = s;
        cls8[r]  = (unsigned char)cls;
        atomicAdd(&s_ccnt[cls], 1);
    }
    __syncthreads();
    if (t == 0) {
        int run = 0;
        for (int c = 0; c < 80; c++) { s_cofs[c] = run; run += s_ccnt[c]; }
        s_cofs[80] = run;
    }
    __syncthreads();
    if (t < 80) s_ccnt[t] = s_cofs[t];   // running positions
    __syncthreads();

    // ---- class-grouped scatter of shifted boxes (sbox overlays dead ck/cv/sk) ----
    #pragma unroll
    for (int rr = 0; rr < TOPKN / SN; rr++) {
        int r = t + SN * rr;
        if (r >= total) continue;
        int cls = (int)((fv[r] >> 16) & 0x7Fu);
        int slot = atomicAdd(&s_ccnt[cls], 1);
        float4 bx = obox[r];
        float c = __fmul_rn((float)cls, 4096.0f);
        sbox[slot] = make_float4(__fadd_rn(bx.x, c), __fadd_rn(bx.y, c),
                                 __fadd_rn(bx.z, c), __fadd_rn(bx.w, c));
        rnk[slot] = (unsigned short)r;
    }
    __syncthreads();

    // ---- within-class pairs flattened across lanes; 32 warps over 80 classes ----
    for (int c = wid; c < 80; c += 32) {
        int lo = s_cofs[c], n = s_cofs[c + 1] - lo;
        int npairs = (n * (n - 1)) >> 1;
        for (int p = lane; p < npairs; p += 32) {
            int j = (int)(0.5f * (1.0f + sqrtf(8.0f * (float)p + 1.0f)));
            while ((j * (j - 1)) >> 1 > p) j--;
            while ((j * (j + 1)) >> 1 <= p) j++;
            int i = p - ((j * (j - 1)) >> 1);

            float4 A = sbox[lo + j];
            float4 B = sbox[lo + i];
            float ltx = fmaxf(A.x, B.x);
            float lty = fmaxf(A.y, B.y);
            float rbx = fminf(A.z, B.z);
            float rby = fminf(A.w, B.w);
            float ww = fmaxf(__fsub_rn(rbx, ltx), 0.0f);
            float hh = fmaxf(__fsub_rn(rby, lty), 0.0f);
            float inter = __fmul_rn(ww, hh);
            if (inter > 0.0f) {
                float areaA = __fmul_rn(__fsub_rn(A.z, A.x), __fsub_rn(A.w, A.y));
                float areaB = __fmul_rn(__fsub_rn(B.z, B.x), __fsub_rn(B.w, B.y));
                float denom = __fadd_rn(__fsub_rn(__fadd_rn(areaA, areaB), inter), 1e-7f);
                bool bit;
                if (inter > __fmul_rn(0.4501f, denom))       bit = true;
                else if (inter <= __fmul_rn(0.4499f, denom)) bit = false;
                else bit = (__fdiv_rn(inter, denom) > 0.45f);
                if (bit) {
                    int ri = rnk[lo + i], rj = rnk[lo + j];
                    int lw = min(ri, rj), hi = max(ri, rj);
                    int pos = atomicAdd(&s_ecnt, 1);
                    if (pos < ECAP)
                        edges[pos] = ((unsigned)lw << 16) | (unsigned)hi;
                }
            }
        }
    }
    __syncthreads();
    int E = min(s_ecnt, ECAP);

    if (t < 32) {
        int base = t * 64;
        s_keep[t] = (total >= base + 64) ? ~0ull
                  : (total <= base) ? 0ull : ((1ull << (total - base)) - 1ull);
    }
    __syncthreads();

    // ---- Jacobi fixpoint (DAG, edges i<j) ----
    int changed;
    do {
        if (t < 32) s_sup[t] = 0ull;
        __syncthreads();
        for (int e = t; e < E; e += SN) {
            unsigned ed = edges[e];
            int i = (int)(ed >> 16), j = (int)(ed & 0xFFFFu);
            if ((s_keep[i >> 6] >> (i & 63)) & 1ull)
                atomicOr(&s_sup[j >> 6], 1ull << (j & 63));
        }
        __syncthreads();
        if (t == 0) s_changed = 0;
        __syncthreads();
        if (t < 32) {
            int base = t * 64;
            u64 valid = (total >= base + 64) ? ~0ull
                      : (total <= base) ? 0ull : ((1ull << (total - base)) - 1ull);
            u64 nk = valid & ~s_sup[t];
            if (nk != s_keep[t]) { s_keep[t] = nk; s_changed = 1; }
        }
        __syncthreads();
        changed = s_changed;
    } while (changed);

    // ---- output ----
    if (wid == 0) {
        unsigned cnt2 = (unsigned)__popcll(s_keep[lane]), incl2 = cnt2;
        #pragma unroll
        for (int d = 1; d < 32; d <<= 1) {
            unsigned n = __shfl_up_sync(FULLM, incl2, d);
            if (lane >= d) incl2 += n;
        }
        s_wbase[lane] = incl2 - cnt2;
        if (lane == 31) s_total = incl2;
    }
    __syncthreads();

    #pragma unroll
    for (int r = 0; r < TOPKN / SN; r++) {
        int gbit = t + SN * r;
        int word = gbit >> 6, bit = gbit & 63;
        u64 kw = s_keep[word];
        if ((kw >> bit) & 1ull) {
            unsigned rank = s_wbase[word] +
                            (unsigned)__popcll(kw & (((u64)1 << bit) - 1ull));
            if (rank < MAXDET) {
                float4 bx = obox[gbit];
                float* o = out + ((size_t)b * MAXDET + rank) * 6;
                o[0] = bx.x; o[1] = bx.y; o[2] = bx.z; o[3] = bx.w;
                o[4] = score[gbit];
                o[5] = (float)cls8[gbit];
            }
        }
    }
    unsigned fillstart = min(s_total, (unsigned)MAXDET);
    for (unsigned m = fillstart + t; m < MAXDET; m += SN) {
        float* o = out + ((size_t)b * MAXDET + m) * 6;
        o[0] = 0.f; o[1] = 0.f; o[2] = 0.f; o[3] = 0.f; o[4] = 0.f; o[5] = -1.f;
    }
}

// ---------------- launch ----------------
extern "C" void kernel_launch(void* const* d_in, const int* in_sizes, int n_in,
                              void* d_out, int out_size) {
    (void)in_sizes; (void)n_in; (void)out_size;
    const float* pred = (const float*)d_in[0];
    float* out = (float*)d_out;

    static bool attr_set = false;
    if (!attr_set) {
        cudaFuncSetAttribute(k_sortnms, cudaFuncAttributeMaxDynamicSharedMemorySize,
                             DYN_TOTAL);
        attr_set = true;
    }

    k_score<<<dim3((NP + IPB - 1) / IPB, BATCH), STH>>>(pred);
    k_sortnms<<<BATCH, SN, DYN_TOTAL>>>(pred, out);
}